// round 5
// baseline (speedup 1.0000x reference)
#include <cuda_runtime.h>
#include <cstdint>

// Time2Vec: out[b,l,d*64+e] = (e==0) ? x*W[d,0]+b[d,0] : sin(x*W[d,e]+b[d,e])
// out: 16,777,216 float4 quads (256MB). Store-path experiment: stage 16KB
// tiles in SMEM (double-buffered) and drain via cp.async.bulk (TMA bulk
// store) in long contiguous bursts, bypassing the per-warp STG/L1tex
// wavefront path that appears to pace the R3 kernel at ~4.8 TB/s.

constexpr int THREADS      = 256;
constexpr int CHUNK_QUADS  = 1024;               // 16 KB per chunk
constexpr int NCHUNK       = 8;                  // 128 KB per CTA
constexpr int CTA_QUADS    = CHUNK_QUADS * NCHUNK;  // 8192
constexpr int N_QUADS      = 1 << 24;
constexpr int BLOCKS       = N_QUADS / CTA_QUADS;   // 2048
constexpr int JQ           = CHUNK_QUADS / THREADS; // 4 quads/thread/chunk

__global__ __launch_bounds__(THREADS, 6)
void time2vec_kernel(const float* __restrict__ x,
                     const float* __restrict__ W,
                     const float* __restrict__ B,
                     float4* __restrict__ out)
{
    __shared__ alignas(128) float4 buf[2][CHUNK_QUADS];   // 2 x 16 KB

    const int tid = threadIdx.x;
    const int cta_base = blockIdx.x * CTA_QUADS;          // multiple of 8192

    // (d, e) depend only on tid (all bases are multiples of 128 quads)
    const int e = (tid & 15) << 2;
    const int d = (tid >> 4) & 7;
    const bool first = (e == 0);

    const float4 w4 = __ldg((const float4*)(W + d * 64 + e));
    const float4 b4 = __ldg((const float4*)(B + d * 64 + e));

    const int xt = tid >> 4;   // thread's x sub-offset (0..15)

    for (int c = 0; c < NCHUNK; c++) {
        const int p = c & 1;
        const int chunk_base = cta_base + c * CHUNK_QUADS;

        // ---- compute 4 quads into registers (overlaps with in-flight TMA) ----
        float4 r[JQ];
        #pragma unroll
        for (int j = 0; j < JQ; j++) {
            const int xb = (chunk_base + j * THREADS) >> 4;  // base mult of 16
            const float xv = __ldcs(&x[xb + xt]);
            const float v0 = fmaf(xv, w4.x, b4.x);
            r[j].x = first ? v0 : __sinf(v0);
            r[j].y = __sinf(fmaf(xv, w4.y, b4.y));
            r[j].z = __sinf(fmaf(xv, w4.z, b4.z));
            r[j].w = __sinf(fmaf(xv, w4.w, b4.w));
        }

        // ---- make sure buffer p's previous TMA drain has finished reading ----
        if (c >= 2) {
            if (tid == 0)
                asm volatile("cp.async.bulk.wait_group.read 1;" ::: "memory");
            __syncthreads();
        }

        // ---- stage in SMEM ----
        #pragma unroll
        for (int j = 0; j < JQ; j++)
            buf[p][j * THREADS + tid] = r[j];
        __syncthreads();   // drains STS; all data visible

        // ---- elected thread launches the bulk store ----
        if (tid == 0) {
            asm volatile("fence.proxy.async.shared::cta;" ::: "memory");
            uint32_t saddr = (uint32_t)__cvta_generic_to_shared(&buf[p][0]);
            asm volatile(
                "cp.async.bulk.global.shared::cta.bulk_group [%0], [%1], %2;"
                :: "l"(out + chunk_base), "r"(saddr),
                   "n"(CHUNK_QUADS * 16)
                : "memory");
            asm volatile("cp.async.bulk.commit_group;" ::: "memory");
        }
    }

    // ensure all bulk stores complete before CTA exit
    if (tid == 0)
        asm volatile("cp.async.bulk.wait_group.read 0;" ::: "memory");
    __syncthreads();
}

extern "C" void kernel_launch(void* const* d_in, const int* in_sizes, int n_in,
                              void* d_out, int out_size)
{
    const float* x = (const float*)d_in[0];
    const float* W = (const float*)d_in[1];
    const float* B = (const float*)d_in[2];
    time2vec_kernel<<<BLOCKS, THREADS>>>(x, W, B, (float4*)d_out);
}

// round 6
// speedup vs baseline: 1.0333x; 1.0333x over previous
#include <cuda_runtime.h>

// Time2Vec: out[b,l,d*64+e] = (e==0) ? x*W[d,0]+b[d,0] : sin(x*W[d,e]+b[d,e])
// x: (32,4096,8) fp32, W/b: (8,64) fp32, out: (32,4096,512) fp32 = 16,777,216 quads.
//
// R5 lesson: TMA bulk store regressed (LTS cap is path-independent; SMEM
// round-trip + serialization cost extra). Back to direct STG.128 (45.15us),
// now PERSISTENT: exactly one wave (148 SMs x 8 CTAs = 1184 blocks), each CTA
// grid-strides over contiguous 32KB tiles -> no wave-transition overhead.
// (d,e) and w4/b4 remain loop-invariant registers (all strides mult of 128 quads).

constexpr int THREADS    = 256;
constexpr int ITER       = 8;
constexpr int TILE_QUADS = THREADS * ITER;            // 2048 quads = 32 KB
constexpr int N_QUADS    = 1 << 24;                   // 16,777,216
constexpr int NTILES     = N_QUADS / TILE_QUADS;      // 8192
constexpr int GRID       = 148 * 8;                   // 1184 = one full wave @ occ 8

__global__ __launch_bounds__(THREADS, 8)
void time2vec_kernel(const float* __restrict__ x,
                     const float* __restrict__ W,
                     const float* __restrict__ B,
                     float4* __restrict__ out)
{
    const int tid = threadIdx.x;

    // loop-invariant coordinates: every tile base is a multiple of 2048 quads
    // and the per-iter stride is 256 quads, so (d,e) depend only on tid.
    const int e = (tid & 15) << 2;        // starting e within [0,64)
    const int d = (tid >> 4) & 7;         // D = 8
    const bool first = (e == 0);          // passthrough lane

    const float4 w4 = __ldg((const float4*)(W + d * 64 + e));
    const float4 b4 = __ldg((const float4*)(B + d * 64 + e));

    const int xt = tid >> 4;              // thread's x sub-offset within 16

    for (int tile = blockIdx.x; tile < NTILES; tile += GRID) {
        const int q0 = tile * TILE_QUADS + tid;

        // front-batch the streaming x loads (each read exactly once)
        float xv[ITER];
        #pragma unroll
        for (int i = 0; i < ITER; i++) {
            const int xb = (tile * TILE_QUADS + i * THREADS) >> 4;
            xv[i] = __ldcs(&x[xb + xt]);
        }

        #pragma unroll
        for (int i = 0; i < ITER; i++) {
            const float v0 = fmaf(xv[i], w4.x, b4.x);
            float4 r;
            r.x = first ? v0 : __sinf(v0);
            r.y = __sinf(fmaf(xv[i], w4.y, b4.y));
            r.z = __sinf(fmaf(xv[i], w4.z, b4.z));
            r.w = __sinf(fmaf(xv[i], w4.w, b4.w));

            __stcs(&out[q0 + i * THREADS], r);   // dense 32KB per tile
        }
    }
}

extern "C" void kernel_launch(void* const* d_in, const int* in_sizes, int n_in,
                              void* d_out, int out_size)
{
    const float* x = (const float*)d_in[0];
    const float* W = (const float*)d_in[1];
    const float* B = (const float*)d_in[2];
    time2vec_kernel<<<GRID, THREADS>>>(x, W, B, (float4*)d_out);
}

// round 7
// speedup vs baseline: 1.0990x; 1.0636x over previous
#include <cuda_runtime.h>
#include <cstdint>

// Time2Vec: out[b,l,d*64+e] = (e==0) ? x*W[d,0]+b[d,0] : sin(x*W[d,e]+b[d,e])
// x: (32,4096,8) fp32, W/b: (8,64) fp32, out: (32,4096,512) fp32.
//
// R6 lesson: persistent CTAs regress (HW block replacement > software loop).
// Back to many short dense blocks (R4 regime). New lever: Blackwell 256-bit
// stores (st.global.v8.f32) -> each thread owns 8 consecutive floats, each
// warp store = 1024B contiguous in ONE instruction, halving LSU/L1tex
// store-front-end work per byte (the highest utilization counter at 72.7%).
//
// Units below: "group" = 8 consecutive output floats. 8,388,608 groups total.
// Thread's group index mod 64 depends only on tid -> (d, e) loop-invariant.

constexpr int THREADS   = 256;
constexpr int ITER      = 8;
constexpr int TILE_GRPS = THREADS * ITER;          // 2048 groups = 64 KB dense/block
constexpr int N_GROUPS  = (1 << 26) / 8;           // 8,388,608
constexpr int BLOCKS    = N_GROUPS / TILE_GRPS;    // 4096

__global__ __launch_bounds__(THREADS)
void time2vec_kernel(const float* __restrict__ x,
                     const float* __restrict__ W,
                     const float* __restrict__ B,
                     float* __restrict__ out)
{
    const int tid = threadIdx.x;
    const int g0  = blockIdx.x * TILE_GRPS + tid;   // tile base mult of 2048

    // loop-invariant coordinates (all group strides are multiples of 64)
    const int e8 = (tid & 7) << 3;       // starting e within [0,64), step 8
    const int d  = (tid >> 3) & 7;       // D = 8
    const bool first = (e8 == 0);        // element 0 of this group is passthrough

    const float4 wa = __ldg((const float4*)(W + d * 64 + e8));
    const float4 wb = __ldg((const float4*)(W + d * 64 + e8 + 4));
    const float4 ba = __ldg((const float4*)(B + d * 64 + e8));
    const float4 bb = __ldg((const float4*)(B + d * 64 + e8 + 4));

    const int xt = tid >> 3;             // x sub-offset (0..31), 8 threads share one x

    #pragma unroll
    for (int i = 0; i < ITER; i++) {
        const int xb = (blockIdx.x * TILE_GRPS + i * THREADS) >> 3;  // mult of 32
        const float xv = __ldcs(&x[xb + xt]);

        const float v0 = fmaf(xv, wa.x, ba.x);
        float r0 = first ? v0 : __sinf(v0);
        float r1 = __sinf(fmaf(xv, wa.y, ba.y));
        float r2 = __sinf(fmaf(xv, wa.z, ba.z));
        float r3 = __sinf(fmaf(xv, wa.w, ba.w));
        float r4 = __sinf(fmaf(xv, wb.x, bb.x));
        float r5 = __sinf(fmaf(xv, wb.y, bb.y));
        float r6 = __sinf(fmaf(xv, wb.z, bb.z));
        float r7 = __sinf(fmaf(xv, wb.w, bb.w));

        float* p = out + (size_t)(g0 + i * THREADS) * 8;  // 32B-aligned
        asm volatile(
            "st.global.cs.v8.f32 [%0], {%1,%2,%3,%4,%5,%6,%7,%8};"
            :: "l"(p),
               "f"(r0), "f"(r1), "f"(r2), "f"(r3),
               "f"(r4), "f"(r5), "f"(r6), "f"(r7)
            : "memory");
    }
}

extern "C" void kernel_launch(void* const* d_in, const int* in_sizes, int n_in,
                              void* d_out, int out_size)
{
    const float* x = (const float*)d_in[0];
    const float* W = (const float*)d_in[1];
    const float* B = (const float*)d_in[2];
    time2vec_kernel<<<BLOCKS, THREADS>>>(x, W, B, (float*)d_out);
}

// round 8
// speedup vs baseline: 1.4430x; 1.3130x over previous
#include <cuda_runtime.h>

// Time2Vec: out[b,l,d*64+e] = (e==0) ? x*W[d,0]+b[d,0] : sin(x*W[d,e]+b[d,e])
// x: (32,4096,8) fp32, W/b: (8,64) fp32, out: (32,4096,512) fp32 = 16,777,216 quads.
//
// Converged design (R2-R7 evidence): pure write-stream kernel at the HBM
// write-bandwidth / LTS floor (~5.6 TB/s). Winning regime = many short-lived
// dense blocks, direct STG.128 with evict-first hints, loop-invariant (d,e)
// so w4/b4 live in registers. This round: 16KB tiles (ITER=4, 16384 blocks)
// for more concurrent CTAs and a shorter per-CTA store-drain tail.

constexpr int N_QUADS     = 1 << 24;                 // 16,777,216
constexpr int THREADS     = 256;
constexpr int ITER        = 4;
constexpr int BLOCK_QUADS = THREADS * ITER;          // 1024 quads = 16 KB contiguous
constexpr int BLOCKS      = N_QUADS / BLOCK_QUADS;   // 16384
constexpr int XITER       = THREADS / 16;            // 16 x-elements per iter step

__global__ __launch_bounds__(THREADS, 8)
void time2vec_kernel(const float* __restrict__ x,
                     const float* __restrict__ W,
                     const float* __restrict__ B,
                     float4* __restrict__ out)
{
    const int q0 = blockIdx.x * BLOCK_QUADS + threadIdx.x;

    // loop-invariant coordinates (block offset mult of 1024, per-iter stride
    // 256 — both multiples of 128 quads -> (d,e) depend only on tid)
    const int e = (q0 & 15) << 2;        // starting e within [0,64)
    const int d = (q0 >> 4) & 7;         // D = 8
    const bool first = (e == 0);         // passthrough lane

    const float4 w4 = __ldg((const float4*)(W + d * 64 + e));
    const float4 b4 = __ldg((const float4*)(B + d * 64 + e));

    const int x0 = q0 >> 4;

    // front-batch the streaming x loads (each read exactly once)
    float xv[ITER];
    #pragma unroll
    for (int i = 0; i < ITER; i++)
        xv[i] = __ldcs(&x[x0 + i * XITER]);

    #pragma unroll
    for (int i = 0; i < ITER; i++) {
        const float v0 = fmaf(xv[i], w4.x, b4.x);
        float4 r;
        r.x = first ? v0 : __sinf(v0);
        r.y = __sinf(fmaf(xv[i], w4.y, b4.y));
        r.z = __sinf(fmaf(xv[i], w4.z, b4.z));
        r.w = __sinf(fmaf(xv[i], w4.w, b4.w));

        __stcs(&out[q0 + i * THREADS], r);   // dense 16KB per block
    }
}

extern "C" void kernel_launch(void* const* d_in, const int* in_sizes, int n_in,
                              void* d_out, int out_size)
{
    const float* x = (const float*)d_in[0];
    const float* W = (const float*)d_in[1];
    const float* B = (const float*)d_in[2];
    time2vec_kernel<<<BLOCKS, THREADS>>>(x, W, B, (float4*)d_out);
}